// round 13
// baseline (speedup 1.0000x reference)
#include <cuda_runtime.h>

typedef unsigned long long u64;

#define NN 64
#define TT 5
#define VV 64
#define FF 256
#define TMID 2          // T//2
#define NSL 8           // f-slices (blocks per graph)
#define FSL (FF / NSL)  // 32 f per slice
#define ABS2_MASK 0x7FFFFFFF7FFFFFFFULL
#define PAD0 33         // xs0 row stride (floats): odd -> conflict-free

__device__ float d_part[(size_t)NSL * NN * VV * VV];  // 8 MB partial-D scratch

__device__ __forceinline__ u64 add2(u64 a, u64 b) {
    u64 d; asm("add.rn.f32x2 %0, %1, %2;" : "=l"(d) : "l"(a), "l"(b)); return d;
}
__device__ __forceinline__ u64 swap2(u64 v) {
    u64 d;
    asm("{.reg .b32 lo, hi; mov.b64 {lo, hi}, %1; mov.b64 %0, {hi, lo};}"
        : "=l"(d) : "l"(v));
    return d;
}
__device__ __forceinline__ float lo2(u64 v) { return __uint_as_float((unsigned)v); }
__device__ __forceinline__ float hi2(u64 v) { return __uint_as_float((unsigned)(v >> 32)); }

// ---------------- Pass 1: partial D over a 32-f slice ----------------
// Grid = 512 (64 graphs x 8 f-slices), 512 threads, 41 KB static smem ->
// 2 blocks/SM (reg-capped), 32 warps/SM. Block computes the FULL 64x64
// partial distance matrix D_fs[i][j] = sum_{f in slice} a_f|y_i - y_j|
// with the diagonal-packed f32x2 loop, writing raw partials to d_part.
// Warp = (tile = w&7 -> rows tile*8..+7, fh = w>>3 -> 16-f half of slice).
__global__ __launch_bounds__(512, 2)
void gl_pass1(const float* __restrict__ x, const float* __restrict__ a) {
    __shared__ float xs0[VV * PAD0];     // raw slice [v][33]     8448 B
    __shared__ float a_s[FSL];           //                        128 B
    __shared__ float xsT[FSL * VV];      //  y = a.*x, [f][v]      8 KB
    __shared__ float xsN[FSL * VV];      // -y                     8 KB
    __shared__ u64   ex[8 * 8 * 32];     // f-half merge          16 KB

    const int b    = blockIdx.x;
    const int n    = b >> 3;         // graph
    const int fs   = b & 7;          // f-slice
    const int tid  = threadIdx.x;
    const int lane = tid & 31;
    const int warp = tid >> 5;

    const float* xm = x + ((size_t)n * TT + TMID) * (size_t)(VV * FF);

    // Phase 1: coalesced LDG.128 of the slice -> xs0 (scalar STS, banks
    // (v>>3 grouping) + 4*(q) + i span 0..31 -> conflict-free).
    {
        int v = tid >> 3, q = tid & 7;
        float4 val = *(const float4*)&xm[v * FF + fs * FSL + q * 4];
        float* dst = &xs0[v * PAD0 + q * 4];
        dst[0] = val.x; dst[1] = val.y; dst[2] = val.z; dst[3] = val.w;
    }
    if (tid < FSL) a_s[tid] = a[fs * FSL + tid];
    __syncthreads();

    // Phase 2: transpose + prescale + negate. Warp w: v = (w&1)*32 + lane,
    // f in [(w>>1)*4, +4). Read banks (33v+f)%32 = (lane+f+c)%32 distinct;
    // write banks (f*64+v)%32 = lane -> both conflict-free.
    {
        int v2 = (warp & 1) * 32 + lane;
        int fb = (warp >> 1) * 4;
        #pragma unroll
        for (int ff = 0; ff < 4; ff++) {
            int f = fb + ff;
            float y = a_s[f] * xs0[v2 * PAD0 + f];
            xsT[f * VV + v2] =  y;
            xsN[f * VV + v2] = -y;
        }
    }
    __syncthreads();

    const int tile   = warp & 7;          // rows tile*8 .. tile*8+7
    const int fh     = warp >> 3;         // f-half of the slice (16 f)
    const int i_base = tile * 8;
    const int j0     = lane << 1;

    const float* pT = xsT + (fh * 16) * VV + i_base;
    const float* pN = xsN + (fh * 16) * VV + j0;

    u64 acc[8];
    #pragma unroll
    for (int k = 0; k < 8; k++) acc[k] = 0;

    // Main loop: 16 f per warp; 2 LDS.128 (bcast) + 1 LDS.64, 24 packed ops,
    // 512 pair-f per iteration.
    #pragma unroll
    for (int f = 0; f < 16; f++) {
        ulonglong2 xiA = *(const ulonglong2*)pT;        // (y_i0,y_i1),(y_i2,y_i3)
        ulonglong2 xiB = *(const ulonglong2*)(pT + 4);  // (y_i4,y_i5),(y_i6,y_i7)
        u64 nj  = *(const u64*)pN;                      // (-y_j0,-y_j1)
        u64 njr = swap2(nj);                            // (-y_j1,-y_j0)

        acc[0] = add2(acc[0], add2(xiA.x, nj ) & ABS2_MASK); // (i0,j0)(i1,j1)
        acc[1] = add2(acc[1], add2(xiA.x, njr) & ABS2_MASK); // (i0,j1)(i1,j0)
        acc[2] = add2(acc[2], add2(xiA.y, nj ) & ABS2_MASK); // (i2,j0)(i3,j1)
        acc[3] = add2(acc[3], add2(xiA.y, njr) & ABS2_MASK); // (i2,j1)(i3,j0)
        acc[4] = add2(acc[4], add2(xiB.x, nj ) & ABS2_MASK); // (i4,j0)(i5,j1)
        acc[5] = add2(acc[5], add2(xiB.x, njr) & ABS2_MASK); // (i4,j1)(i5,j0)
        acc[6] = add2(acc[6], add2(xiB.y, nj ) & ABS2_MASK); // (i6,j0)(i7,j1)
        acc[7] = add2(acc[7], add2(xiB.y, njr) & ABS2_MASK); // (i6,j1)(i7,j0)

        pT += VV; pN += VV;
    }

    // Merge the two f-halves (fh1 publishes, fh0 adds), then store partials.
    if (fh) {
        u64* p = ex + tile * 32 + lane;
        #pragma unroll
        for (int k = 0; k < 8; k++) p[k * 256] = acc[k];
    }
    __syncthreads();
    if (fh) return;

    {
        const u64* p = ex + tile * 32 + lane;
        #pragma unroll
        for (int k = 0; k < 8; k++) acc[k] = add2(acc[k], p[k * 256]);
    }

    // Store raw partial D (no exp): row 2r gets (lo acc[2r], lo acc[2r+1]);
    // row 2r+1 gets (hi acc[2r+1], hi acc[2r]). Coalesced float2 stores.
    float* db = d_part + (((size_t)fs * NN + n) * VV + i_base) * VV + j0;
    #pragma unroll
    for (int r = 0; r < 4; r++) {
        *(float2*)(db + (2 * r)     * VV) =
            make_float2(lo2(acc[2 * r]), lo2(acc[2 * r + 1]));
        *(float2*)(db + (2 * r + 1) * VV) =
            make_float2(hi2(acc[2 * r + 1]), hi2(acc[2 * r]));
    }
}

// ---------------- Pass 2: reduce slices, exp, normalize ----------------
// Grid = 512, 256 threads; warp owns one (n,i) row: sum the 8 f-slice
// partials, exponentiate, row-sum (== reference column sum by the exact
// bitwise symmetry of D), normalize, store.
__global__ __launch_bounds__(256)
void gl_pass2(float* __restrict__ out) {
    const int lane = threadIdx.x & 31;
    const int row  = blockIdx.x * 8 + (threadIdx.x >> 5);   // 0..4095 = n*64+i

    float sx = 0.f, sy = 0.f;
    #pragma unroll
    for (int fs = 0; fs < NSL; fs++) {
        float2 v = *(const float2*)&d_part[((size_t)fs * (NN * VV) + row) * VV
                                           + 2 * lane];
        sx += v.x; sy += v.y;
    }

    const float LOG2E = 1.4426950408889634f;
    float e0 = exp2f(sx * LOG2E);
    float e1 = exp2f(sy * LOG2E);

    float r = e0 + e1;
    #pragma unroll
    for (int off = 16; off > 0; off >>= 1)
        r += __shfl_xor_sync(0xFFFFFFFFu, r, off);
    float inv = 1.0f / r;

    *(float2*)&out[(size_t)row * VV + 2 * lane] = make_float2(e0 * inv, e1 * inv);
}

extern "C" void kernel_launch(void* const* d_in, const int* in_sizes, int n_in,
                              void* d_out, int out_size) {
    const float* x = (const float*)d_in[0];   // (64,5,64,256) float32
    const float* a = (const float*)d_in[1];   // (256,1) float32
    float* out = (float*)d_out;               // (64,64,64) float32

    gl_pass1<<<NN * NSL, 512>>>(x, a);        // 512 blocks
    gl_pass2<<<(NN * VV) / 8, 256>>>(out);    // 512 blocks
}

// round 14
// speedup vs baseline: 1.0869x; 1.0869x over previous
#include <cuda_runtime.h>

typedef unsigned long long u64;

#define NN 64
#define TT 5
#define VV 64
#define FF 256
#define TMID 2   // T//2
#define ABS2_MASK 0x7FFFFFFF7FFFFFFFULL
#define NEG1X2    0xBF800000BF800000ULL   // packed (-1.0f, -1.0f)
#define PAD 260  // xs0 row stride in floats: %4==0 for STS.128 alignment

__device__ __forceinline__ u64 add2(u64 a, u64 b) {
    u64 d; asm("add.rn.f32x2 %0, %1, %2;" : "=l"(d) : "l"(a), "l"(b)); return d;
}
__device__ __forceinline__ u64 fma2(u64 a, u64 b, u64 c) {
    u64 d; asm("fma.rn.f32x2 %0, %1, %2, %3;" : "=l"(d) : "l"(a), "l"(b), "l"(c)); return d;
}
__device__ __forceinline__ u64 swap2(u64 v) {
    u64 d;
    asm("{.reg .b32 lo, hi; mov.b64 {lo, hi}, %1; mov.b64 %0, {hi, lo};}"
        : "=l"(d) : "l"(v));
    return d;
}
__device__ __forceinline__ float lo2(u64 v) { return __uint_as_float((unsigned)v); }
__device__ __forceinline__ float hi2(u64 v) { return __uint_as_float((unsigned)(v >> 32)); }

// Grid = 128 (64 graphs x 2 halves), 512 threads = 16 warps, single kernel.
// a_f >= 0, so a_f*|x_i - x_j| == |y_i - y_j| with y = a.*x (staged once).
// The subtraction sign comes from fma.rn.f32x2(y_j, -1, y_i), so only ONE
// staged array (xsT) is needed — no negated copy.
//
// Block owns 32 complete rows i of graph n's 64x64 similarity matrix; the
// column-sum denominator equals the row sum by exact (bitwise) symmetry of S.
// Warp = (tile = w&1 -> 16 rows, fq = w>>1 -> 32-f slice). Lane owns
// j = 2l, 2l+1; diagonal f32x2 packing; 16 accumulators. Per iter:
// 4 LDS.128 (xi bcast) + 1 LDS.64 (xj) + 48 packed math, 1024 pair-f.
__global__ __launch_bounds__(512, 1)
void gl_kernel(const float* __restrict__ x,
               const float* __restrict__ a,
               float* __restrict__ out) {
    extern __shared__ float sm[];
    float* xs0 = sm;                          // [VV][PAD] raw slice,   65 KB
    u64*   ex  = (u64*)sm;                    // aliases xs0 (dead after stage)
    float* a_s = sm + VV * PAD;               // [FF]                    1 KB
    float* xsT = a_s + FF;                    // [FF][VV]  y = a.*x,    64 KB

    const int b    = blockIdx.x;
    const int n    = b >> 1;
    const int half = b & 1;
    const int tid  = threadIdx.x;
    const int lane = tid & 31;
    const int warp = tid >> 5;

    const float* xm = x + ((size_t)n * TT + TMID) * (size_t)(VV * FF);

    // ---- Phase 1: coalesced copy x[v][f] -> xs0[v][f] (padded rows) ----
    const float4* x4 = (const float4*)xm;
    #pragma unroll
    for (int idx = tid; idx < VV * (FF / 4); idx += 512) {
        int v  = idx >> 6;          // FF/4 == 64
        int f4 = idx & 63;          // consecutive across lanes -> coalesced
        float4 val = x4[idx];
        *(float4*)&xs0[v * PAD + f4 * 4] = val;   // STS.128, conflict-free
    }
    if (tid < FF) a_s[tid] = a[tid];
    __syncthreads();

    // ---- Phase 2: diagonal transpose + prescale ----
    // warp -> (h = warp&1: v-half, fblk = warp>>1: 32-f block)
    // lane l: v = 32h + l, f = 32*fblk + ((29l + s) & 31).
    // LDS bank = (260v+f)%32 = (l+s)%32; STS bank = (64f+v)%32 = l. Both CF.
    {
        const int h    = warp & 1;
        const int fblk = warp >> 1;
        const int v    = 32 * h + lane;
        const int sig  = (29 * lane) & 31;
        const float* src = xs0 + v * PAD + fblk * 32;
        #pragma unroll 8
        for (int s = 0; s < 32; s++) {
            int fo = (sig + s) & 31;
            int f  = fblk * 32 + fo;
            xsT[f * VV + v] = a_s[f] * src[fo];
        }
    }
    __syncthreads();

    const int tile   = warp & 1;                // rows tile*16 .. +15
    const int fq     = warp >> 1;               // f-slice 0..7 (32 f each)
    const int i_base = half * 32 + tile * 16;
    const int j0     = lane << 1;

    const float* pT = xsT + (fq * 32) * VV + i_base;
    const float* pN = xsT + (fq * 32) * VV + j0;

    u64 acc[16];
    #pragma unroll
    for (int k = 0; k < 16; k++) acc[k] = 0;

    const u64 neg1 = NEG1X2;

    // ---- Main loop: 32 f per warp; 4 LDS.128 + 1 LDS.64 + 48 packed ops,
    //      covering 1024 pair-f per iteration. ----
    #pragma unroll 4
    for (int f = 0; f < 32; f++) {
        ulonglong2 xiA = *(const ulonglong2*)(pT + 0);   // (y_i0,y_i1),(y_i2,y_i3)
        ulonglong2 xiB = *(const ulonglong2*)(pT + 4);   // i4..i7
        ulonglong2 xiC = *(const ulonglong2*)(pT + 8);   // i8..i11
        ulonglong2 xiD = *(const ulonglong2*)(pT + 12);  // i12..i15
        u64 xj  = *(const u64*)pN;                       // (y_j0,y_j1)
        u64 xjr = swap2(xj);                             // (y_j1,y_j0)

        acc[ 0] = add2(acc[ 0], fma2(xj,  neg1, xiA.x) & ABS2_MASK);
        acc[ 1] = add2(acc[ 1], fma2(xjr, neg1, xiA.x) & ABS2_MASK);
        acc[ 2] = add2(acc[ 2], fma2(xj,  neg1, xiA.y) & ABS2_MASK);
        acc[ 3] = add2(acc[ 3], fma2(xjr, neg1, xiA.y) & ABS2_MASK);
        acc[ 4] = add2(acc[ 4], fma2(xj,  neg1, xiB.x) & ABS2_MASK);
        acc[ 5] = add2(acc[ 5], fma2(xjr, neg1, xiB.x) & ABS2_MASK);
        acc[ 6] = add2(acc[ 6], fma2(xj,  neg1, xiB.y) & ABS2_MASK);
        acc[ 7] = add2(acc[ 7], fma2(xjr, neg1, xiB.y) & ABS2_MASK);
        acc[ 8] = add2(acc[ 8], fma2(xj,  neg1, xiC.x) & ABS2_MASK);
        acc[ 9] = add2(acc[ 9], fma2(xjr, neg1, xiC.x) & ABS2_MASK);
        acc[10] = add2(acc[10], fma2(xj,  neg1, xiC.y) & ABS2_MASK);
        acc[11] = add2(acc[11], fma2(xjr, neg1, xiC.y) & ABS2_MASK);
        acc[12] = add2(acc[12], fma2(xj,  neg1, xiD.x) & ABS2_MASK);
        acc[13] = add2(acc[13], fma2(xjr, neg1, xiD.x) & ABS2_MASK);
        acc[14] = add2(acc[14], fma2(xj,  neg1, xiD.y) & ABS2_MASK);
        acc[15] = add2(acc[15], fma2(xjr, neg1, xiD.y) & ABS2_MASK);

        pT += VV; pN += VV;
    }

    // ---- Merge f-slices: fq>0 publish, fq==0 adds (ex aliases dead xs0) ----
    // ex index: ((fq-1)*2 + tile)*512 + k*32 + lane  (8B lane stride: CF)
    if (fq) {
        u64* p = ex + ((fq - 1) * 2 + tile) * 512 + lane;
        #pragma unroll
        for (int k = 0; k < 16; k++) p[k * 32] = acc[k];
    }
    __syncthreads();
    if (fq) return;

    {
        #pragma unroll
        for (int q = 1; q < 8; q++) {
            const u64* p = ex + ((q - 1) * 2 + tile) * 512 + lane;
            #pragma unroll
            for (int k = 0; k < 16; k++) acc[k] = add2(acc[k], p[k * 32]);
        }
    }

    // ---- exp, per-row warp reduction (row sum == reference column sum) ----
    const float LOG2E = 1.4426950408889634f;
    float sl[16], sh[16];
    #pragma unroll
    for (int k = 0; k < 16; k++) {
        sl[k] = exp2f(lo2(acc[k]) * LOG2E);
        sh[k] = exp2f(hi2(acc[k]) * LOG2E);
    }
    // row 2r  : j0 -> sl[2r],   j1 -> sl[2r+1]
    // row 2r+1: j0 -> sh[2r+1], j1 -> sh[2r]
    float p[16];
    #pragma unroll
    for (int r = 0; r < 8; r++) {
        p[2 * r]     = sl[2 * r] + sl[2 * r + 1];
        p[2 * r + 1] = sh[2 * r] + sh[2 * r + 1];
    }
    #pragma unroll
    for (int off = 16; off > 0; off >>= 1) {
        #pragma unroll
        for (int r = 0; r < 16; r++)
            p[r] += __shfl_xor_sync(0xFFFFFFFFu, p[r], off);
    }

    float* ob = out + ((size_t)(n * VV + i_base)) * VV + j0;
    #pragma unroll
    for (int r = 0; r < 8; r++) {
        float inv0 = 1.0f / p[2 * r];
        float inv1 = 1.0f / p[2 * r + 1];
        *(float2*)(ob + (2 * r)     * VV) =
            make_float2(sl[2 * r] * inv0, sl[2 * r + 1] * inv0);
        *(float2*)(ob + (2 * r + 1) * VV) =
            make_float2(sh[2 * r + 1] * inv1, sh[2 * r] * inv1);
    }
}

extern "C" void kernel_launch(void* const* d_in, const int* in_sizes, int n_in,
                              void* d_out, int out_size) {
    const float* x = (const float*)d_in[0];   // (64,5,64,256) float32
    const float* a = (const float*)d_in[1];   // (256,1) float32
    float* out = (float*)d_out;               // (64,64,64) float32

    const int smem_bytes = (VV * PAD + FF + FF * VV) * (int)sizeof(float);
    cudaFuncSetAttribute(gl_kernel, cudaFuncAttributeMaxDynamicSharedMemorySize,
                         smem_bytes);
    gl_kernel<<<NN * 2, 512, smem_bytes>>>(x, a, out);
}

// round 16
// speedup vs baseline: 1.1056x; 1.0172x over previous
#include <cuda_runtime.h>

typedef unsigned long long u64;

#define NN 64
#define TT 5
#define VV 64
#define FF 256
#define TMID 2   // T//2
#define ABS2_MASK 0x7FFFFFFF7FFFFFFFULL
#define NEG1X2    0xBF800000BF800000ULL   // packed (-1.0f, -1.0f)
#define PAD 260  // xs0h row stride in floats: %4==0 for STS.128 alignment

__device__ __forceinline__ u64 add2(u64 a, u64 b) {
    u64 d; asm("add.rn.f32x2 %0, %1, %2;" : "=l"(d) : "l"(a), "l"(b)); return d;
}
__device__ __forceinline__ u64 fma2(u64 a, u64 b, u64 c) {
    u64 d; asm("fma.rn.f32x2 %0, %1, %2, %3;" : "=l"(d) : "l"(a), "l"(b), "l"(c)); return d;
}
__device__ __forceinline__ u64 swap2(u64 v) {
    u64 d;
    asm("{.reg .b32 lo, hi; mov.b64 {lo, hi}, %1; mov.b64 %0, {hi, lo};}"
        : "=l"(d) : "l"(v));
    return d;
}
__device__ __forceinline__ float lo2(u64 v) { return __uint_as_float((unsigned)v); }
__device__ __forceinline__ float hi2(u64 v) { return __uint_as_float((unsigned)(v >> 32)); }

// Grid = 256 (64 graphs x 4 row-quarters), 512 threads, ~98 KB smem ->
// 2 blocks per SM (8 warps/SMSP), so independent blocks overlap each
// other's staging/merge/epilogue phases with main-loop math.
//
// a_f >= 0, so a_f|x_i - x_j| = |y_i - y_j|, y = a.*x (staged once in xsT;
// the sign comes from fma.rn.f32x2(y_j, -1, y_i) — no negated copy).
// Block owns 16 complete rows of graph n's 64x64 matrix; the column-sum
// denominator equals the row sum by exact (bitwise) symmetry of S.
// Warp = (tile = w&1 -> 8 rows, fq = w>>1 -> 32-f slice); lane owns
// j = 2l, 2l+1; diagonal f32x2 packing, 8 accumulators.
//
// Staging: TWO v-chunks through a 33 KB padded buffer (coalesced LDG.128 +
// CF STS.128, then diagonal-permuted CF reads -> prescale -> CF STS into
// xsT[f][v]). The merge buffer ex aliases the dead staging buffer.
__global__ __launch_bounds__(512, 2)
void gl_kernel(const float* __restrict__ x,
               const float* __restrict__ a,
               float* __restrict__ out) {
    extern __shared__ float sm[];
    float* xs0h = sm;                         // [32][PAD] chunk buf,  33.3 KB
    u64*   ex   = (u64*)sm;                   // aliases xs0h (dead after stage)
    float* a_s  = sm + 32 * PAD;              // [FF]                     1 KB
    float* xsT  = a_s + FF;                   // [FF][VV]  y = a.*x,     64 KB

    const int b       = blockIdx.x;
    const int n       = b >> 2;
    const int quarter = b & 3;
    const int tid     = threadIdx.x;
    const int lane    = tid & 31;
    const int warp    = tid >> 5;

    const float* xm = x + ((size_t)n * TT + TMID) * (size_t)(VV * FF);
    const float4* x4 = (const float4*)xm;

    if (tid < FF) a_s[tid] = a[tid];

    // ---- Staging: two chunks of 32 v-rows each ----
    #pragma unroll
    for (int c = 0; c < 2; c++) {
        // Phase 1: coalesced copy x[c*32+v][f] -> xs0h[v][f] (padded rows)
        #pragma unroll
        for (int it = 0; it < 4; it++) {
            int idx = tid + it * 512;            // 0 .. 2047
            int v   = idx >> 6;                  // 0..31 (fixed per warp)
            int f4  = idx & 63;                  // spans 32 per warp
            float4 val = x4[(c * 32 + v) * (FF / 4) + f4];
            *(float4*)&xs0h[v * PAD + f4 * 4] = val;   // STS.128, CF
        }
        __syncthreads();

        // Phase 2: diagonal transpose + prescale.
        // warp -> (fblk = w&7: 32-f block, sh = w>>3: 16-s half)
        // lane l: v_local = l, f = 32*fblk + ((29l + s) & 31).
        // read bank (260l+f)%32 = (l+s)%32 ; write bank (64f + c*32+l)%32 = l.
        {
            const int fblk = warp & 7;
            const int sh   = warp >> 3;
            const int sig  = (29 * lane) & 31;
            const float* src = xs0h + lane * PAD + fblk * 32;
            float* dst = xsT + c * 32 + lane;
            #pragma unroll 8
            for (int s = sh * 16; s < sh * 16 + 16; s++) {
                int fo = (sig + s) & 31;
                int f  = fblk * 32 + fo;
                dst[f * VV] = a_s[f] * src[fo];
            }
        }
        __syncthreads();
    }

    const int tile   = warp & 1;                   // rows tile*8 .. +7
    const int fq     = warp >> 1;                  // f-slice 0..7 (32 f)
    const int i_base = quarter * 16 + tile * 8;    // global row base
    const int j0     = lane << 1;

    const float* pT = xsT + (fq * 32) * VV + i_base;
    const float* pN = xsT + (fq * 32) * VV + j0;

    u64 acc[8];
    #pragma unroll
    for (int k = 0; k < 8; k++) acc[k] = 0;

    const u64 neg1 = NEG1X2;

    // ---- Main loop: 32 f per warp; 2 LDS.128 + 1 LDS.64, 32 packed ops,
    //      512 pair-f per iteration. ----
    #pragma unroll 4
    for (int f = 0; f < 32; f++) {
        ulonglong2 xiA = *(const ulonglong2*)pT;        // i0..i3 (broadcast)
        ulonglong2 xiB = *(const ulonglong2*)(pT + 4);  // i4..i7
        u64 xj  = *(const u64*)pN;                      // (y_j0,y_j1)
        u64 xjr = swap2(xj);                            // (y_j1,y_j0)

        acc[0] = add2(acc[0], fma2(xj,  neg1, xiA.x) & ABS2_MASK); // (i0,j0)(i1,j1)
        acc[1] = add2(acc[1], fma2(xjr, neg1, xiA.x) & ABS2_MASK); // (i0,j1)(i1,j0)
        acc[2] = add2(acc[2], fma2(xj,  neg1, xiA.y) & ABS2_MASK); // (i2,j0)(i3,j1)
        acc[3] = add2(acc[3], fma2(xjr, neg1, xiA.y) & ABS2_MASK); // (i2,j1)(i3,j0)
        acc[4] = add2(acc[4], fma2(xj,  neg1, xiB.x) & ABS2_MASK); // (i4,j0)(i5,j1)
        acc[5] = add2(acc[5], fma2(xjr, neg1, xiB.x) & ABS2_MASK); // (i4,j1)(i5,j0)
        acc[6] = add2(acc[6], fma2(xj,  neg1, xiB.y) & ABS2_MASK); // (i6,j0)(i7,j1)
        acc[7] = add2(acc[7], fma2(xjr, neg1, xiB.y) & ABS2_MASK); // (i6,j1)(i7,j0)

        pT += VV; pN += VV;
    }

    // ---- Merge f-slices: fq>0 publish, fq==0 adds (ex aliases xs0h) ----
    // slab ((fq-1)*2 + tile) of 256 u64; within: k*32 + lane (8B stride, CF)
    if (fq) {
        u64* p = ex + ((fq - 1) * 2 + tile) * 256 + lane;
        #pragma unroll
        for (int k = 0; k < 8; k++) p[k * 32] = acc[k];
    }
    __syncthreads();
    if (fq) return;

    {
        #pragma unroll
        for (int q = 1; q < 8; q++) {
            const u64* p = ex + ((q - 1) * 2 + tile) * 256 + lane;
            #pragma unroll
            for (int k = 0; k < 8; k++) acc[k] = add2(acc[k], p[k * 32]);
        }
    }

    // ---- exp, per-row warp reduction (row sum == reference column sum) ----
    const float LOG2E = 1.4426950408889634f;
    float sl[8], sh[8];
    #pragma unroll
    for (int k = 0; k < 8; k++) {
        sl[k] = exp2f(lo2(acc[k]) * LOG2E);
        sh[k] = exp2f(hi2(acc[k]) * LOG2E);
    }
    // row 2r  : j0 -> sl[2r],   j1 -> sl[2r+1]
    // row 2r+1: j0 -> sh[2r+1], j1 -> sh[2r]
    float p[8];
    #pragma unroll
    for (int r = 0; r < 4; r++) {
        p[2 * r]     = sl[2 * r] + sl[2 * r + 1];
        p[2 * r + 1] = sh[2 * r] + sh[2 * r + 1];
    }
    #pragma unroll
    for (int off = 16; off > 0; off >>= 1) {
        #pragma unroll
        for (int r = 0; r < 8; r++)
            p[r] += __shfl_xor_sync(0xFFFFFFFFu, p[r], off);
    }

    float* ob = out + ((size_t)(n * VV + i_base)) * VV + j0;
    #pragma unroll
    for (int r = 0; r < 4; r++) {
        float inv0 = 1.0f / p[2 * r];
        float inv1 = 1.0f / p[2 * r + 1];
        *(float2*)(ob + (2 * r)     * VV) =
            make_float2(sl[2 * r] * inv0, sl[2 * r + 1] * inv0);
        *(float2*)(ob + (2 * r + 1) * VV) =
            make_float2(sh[2 * r + 1] * inv1, sh[2 * r] * inv1);
    }
}

extern "C" void kernel_launch(void* const* d_in, const int* in_sizes, int n_in,
                              void* d_out, int out_size) {
    const float* x = (const float*)d_in[0];   // (64,5,64,256) float32
    const float* a = (const float*)d_in[1];   // (256,1) float32
    float* out = (float*)d_out;               // (64,64,64) float32

    const int smem_bytes = (32 * PAD + FF + FF * VV) * (int)sizeof(float);
    cudaFuncSetAttribute(gl_kernel, cudaFuncAttributeMaxDynamicSharedMemorySize,
                         smem_bytes);
    gl_kernel<<<NN * 4, 512, smem_bytes>>>(x, a, out);
}

// round 17
// speedup vs baseline: 1.1080x; 1.0022x over previous
#include <cuda_runtime.h>

typedef unsigned long long u64;

#define NN 64
#define TT 5
#define VV 64
#define FF 256
#define TMID 2   // T//2
#define ABS2_MASK 0x7FFFFFFF7FFFFFFFULL
#define PAD 260  // xs0 row stride in floats: %4==0 for STS.128 alignment

__device__ __forceinline__ u64 add2(u64 a, u64 b) {
    u64 d; asm("add.rn.f32x2 %0, %1, %2;" : "=l"(d) : "l"(a), "l"(b)); return d;
}
__device__ __forceinline__ u64 swap2(u64 v) {
    u64 d;
    asm("{.reg .b32 lo, hi; mov.b64 {lo, hi}, %1; mov.b64 %0, {hi, lo};}"
        : "=l"(d) : "l"(v));
    return d;
}
__device__ __forceinline__ float lo2(u64 v) { return __uint_as_float((unsigned)v); }
__device__ __forceinline__ float hi2(u64 v) { return __uint_as_float((unsigned)(v >> 32)); }

// Grid = 128 (64 graphs x 2 halves), 512 threads = 16 warps. R11 skeleton
// (best kernel so far) + explicit register double-buffering in the main loop
// so the 29-cycle LDS latency is covered by prefetch instead of stalling.
//
// a_f >= 0, so a_f*|x_i-x_j| = |y_i-y_j|, y = a.*x; staged as xsT (y) and
// xsN (-y) so the diff is a 2-source add.rn.f32x2 (avoids FFMA2's 3x64-bit
// register-bank rt penalty). Abs via 64-bit sign-mask AND (alu pipe).
// Block owns 32 complete rows; column-sum denominator == row sum by exact
// bitwise symmetry of S. Warp = (tile = w&3 -> 8 rows, fq = w>>2 -> 64-f
// quarter); lane owns j = 2l, 2l+1; diagonal f32x2 packing, 8 accumulators.
__global__ __launch_bounds__(512, 1)
void gl_kernel(const float* __restrict__ x,
               const float* __restrict__ a,
               float* __restrict__ out) {
    extern __shared__ float sm[];
    float* xs0 = sm;                          // [VV][PAD] raw slice,   65 KB
    u64*   ex  = (u64*)sm;                    // aliases xs0 (dead after stage)
    float* a_s = sm + VV * PAD;               // [FF]                    1 KB
    float* xsT = a_s + FF;                    // [FF][VV]  y = a.*x,    64 KB
    float* xsN = xsT + FF * VV;               // [FF][VV] -y,           64 KB
    // + VV floats guard pad after xsN for the last prefetch (allocated below)

    const int b    = blockIdx.x;
    const int n    = b >> 1;
    const int half = b & 1;
    const int tid  = threadIdx.x;
    const int lane = tid & 31;
    const int warp = tid >> 5;

    const float* xm = x + ((size_t)n * TT + TMID) * (size_t)(VV * FF);

    // ---- Phase 1: coalesced copy x[v][f] -> xs0[v][f] (padded rows) ----
    const float4* x4 = (const float4*)xm;
    #pragma unroll
    for (int idx = tid; idx < VV * (FF / 4); idx += 512) {
        int v  = idx >> 6;          // FF/4 == 64
        int f4 = idx & 63;          // consecutive across lanes -> coalesced
        float4 val = x4[idx];
        *(float4*)&xs0[v * PAD + f4 * 4] = val;   // STS.128, conflict-free
    }
    if (tid < FF) a_s[tid] = a[tid];
    __syncthreads();

    // ---- Phase 2: diagonal transpose + prescale + negate ----
    // warp -> (h = warp&1: v-half, fblk = warp>>1: 32-f block)
    // lane l: v = 32h + l, f = 32*fblk + ((29l + s) & 31).
    // LDS bank = (260v+f)%32 = (l+s)%32; STS bank = (64f+v)%32 = l. Both CF.
    {
        const int h    = warp & 1;
        const int fblk = warp >> 1;
        const int v    = 32 * h + lane;
        const int sig  = (29 * lane) & 31;
        const float* src = xs0 + v * PAD + fblk * 32;
        #pragma unroll 8
        for (int s = 0; s < 32; s++) {
            int fo = (sig + s) & 31;
            int f  = fblk * 32 + fo;
            float y = a_s[f] * src[fo];
            xsT[f * VV + v] =  y;
            xsN[f * VV + v] = -y;
        }
    }
    __syncthreads();

    const int tile   = warp & 3;                // rows tile*8 .. +7
    const int fq     = warp >> 2;               // f-quarter 0..3 (64 f each)
    const int i_base = half * 32 + tile * 8;
    const int j0     = lane << 1;

    const float* pT = xsT + (fq * 64) * VV + i_base;
    const float* pN = xsN + (fq * 64) * VV + j0;

    u64 acc[8];
    #pragma unroll
    for (int k = 0; k < 8; k++) acc[k] = 0;

    // ---- Software-pipelined main loop: prefetch f+1 while computing f.
    //      Per iter: 2 LDS.128 + 1 LDS.64 (prefetch), 24 packed ops; 512
    //      pair-f. Last iter prefetches into the guard pad (harmless). ----
    ulonglong2 xiA = *(const ulonglong2*)pT;        // i0..i3 (broadcast)
    ulonglong2 xiB = *(const ulonglong2*)(pT + 4);  // i4..i7
    u64        nj  = *(const u64*)pN;               // (-y_j0,-y_j1)

    #pragma unroll 4
    for (int f = 0; f < 64; f++) {
        pT += VV; pN += VV;
        ulonglong2 nxiA = *(const ulonglong2*)pT;        // prefetch f+1
        ulonglong2 nxiB = *(const ulonglong2*)(pT + 4);
        u64        nnj  = *(const u64*)pN;

        u64 njr = swap2(nj);                             // (-y_j1,-y_j0)

        acc[0] = add2(acc[0], add2(xiA.x, nj ) & ABS2_MASK); // (i0,j0)(i1,j1)
        acc[1] = add2(acc[1], add2(xiA.x, njr) & ABS2_MASK); // (i0,j1)(i1,j0)
        acc[2] = add2(acc[2], add2(xiA.y, nj ) & ABS2_MASK); // (i2,j0)(i3,j1)
        acc[3] = add2(acc[3], add2(xiA.y, njr) & ABS2_MASK); // (i2,j1)(i3,j0)
        acc[4] = add2(acc[4], add2(xiB.x, nj ) & ABS2_MASK); // (i4,j0)(i5,j1)
        acc[5] = add2(acc[5], add2(xiB.x, njr) & ABS2_MASK); // (i4,j1)(i5,j0)
        acc[6] = add2(acc[6], add2(xiB.y, nj ) & ABS2_MASK); // (i6,j0)(i7,j1)
        acc[7] = add2(acc[7], add2(xiB.y, njr) & ABS2_MASK); // (i6,j1)(i7,j0)

        xiA = nxiA; xiB = nxiB; nj = nnj;
    }

    // ---- Merge f-quarters: fq>0 publish, fq==0 adds (ex aliases xs0) ----
    // slab ((fq-1)*4 + tile) of 256 u64; within: k*32 + lane (8B stride, CF)
    if (fq) {
        u64* p = ex + ((fq - 1) * 4 + tile) * 256 + lane;
        #pragma unroll
        for (int k = 0; k < 8; k++) p[k * 32] = acc[k];
    }
    __syncthreads();
    if (fq) return;

    {
        #pragma unroll
        for (int q = 1; q < 4; q++) {
            const u64* p = ex + ((q - 1) * 4 + tile) * 256 + lane;
            #pragma unroll
            for (int k = 0; k < 8; k++) acc[k] = add2(acc[k], p[k * 32]);
        }
    }

    // ---- exp, per-row warp reduction (row sum == reference column sum) ----
    const float LOG2E = 1.4426950408889634f;
    float sl[8], sh[8];
    #pragma unroll
    for (int k = 0; k < 8; k++) {
        sl[k] = exp2f(lo2(acc[k]) * LOG2E);
        sh[k] = exp2f(hi2(acc[k]) * LOG2E);
    }
    // row 2r  : j0 -> sl[2r],   j1 -> sl[2r+1]
    // row 2r+1: j0 -> sh[2r+1], j1 -> sh[2r]
    float p[8];
    #pragma unroll
    for (int r = 0; r < 4; r++) {
        p[2 * r]     = sl[2 * r] + sl[2 * r + 1];
        p[2 * r + 1] = sh[2 * r] + sh[2 * r + 1];
    }
    #pragma unroll
    for (int off = 16; off > 0; off >>= 1) {
        #pragma unroll
        for (int r = 0; r < 8; r++)
            p[r] += __shfl_xor_sync(0xFFFFFFFFu, p[r], off);
    }

    float* ob = out + ((size_t)(n * VV + i_base)) * VV + j0;
    #pragma unroll
    for (int r = 0; r < 4; r++) {
        float inv0 = 1.0f / p[2 * r];
        float inv1 = 1.0f / p[2 * r + 1];
        *(float2*)(ob + (2 * r)     * VV) =
            make_float2(sl[2 * r] * inv0, sl[2 * r + 1] * inv0);
        *(float2*)(ob + (2 * r + 1) * VV) =
            make_float2(sh[2 * r + 1] * inv1, sh[2 * r] * inv1);
    }
}

extern "C" void kernel_launch(void* const* d_in, const int* in_sizes, int n_in,
                              void* d_out, int out_size) {
    const float* x = (const float*)d_in[0];   // (64,5,64,256) float32
    const float* a = (const float*)d_in[1];   // (256,1) float32
    float* out = (float*)d_out;               // (64,64,64) float32

    // xs0 + a_s + xsT + xsN + VV-float guard pad for the last prefetch
    const int smem_bytes = (VV * PAD + FF + 2 * FF * VV + VV)
                         * (int)sizeof(float);
    cudaFuncSetAttribute(gl_kernel, cudaFuncAttributeMaxDynamicSharedMemorySize,
                         smem_bytes);
    gl_kernel<<<NN * 2, 512, smem_bytes>>>(x, a, out);
}